// round 1
// baseline (speedup 1.0000x reference)
#include <cuda_runtime.h>
#include <cstdint>

// Fused 9-layer MLP (NeRF-style), fp32, persistent per-tile CTA.
// N=262144 rows, IN=39, H=256, OUT=4.
// Tile: M=64 rows per CTA, 256 threads. Activations ping-pong in smem (K-major),
// weights streamed in 32-row chunks via cp.async double buffer.
// Math via packed fma.rn.f32x2 (2 fp32 FMAs / instr on sm_103a).

#define THREADS 256
#define M_TILE  64
#define KC      32

#define NROWS   262144
#define IN_DIM  39
#define HID     256
#define OUT_DIM 4

typedef unsigned long long u64;

__device__ __forceinline__ u64 pk2(float lo, float hi) {
    u64 r;
    asm("mov.b64 %0, {%1, %2};" : "=l"(r) : "f"(lo), "f"(hi));
    return r;
}
__device__ __forceinline__ u64 fma2(u64 a, u64 b, u64 c) {
    u64 d;
    asm("fma.rn.f32x2 %0, %1, %2, %3;" : "=l"(d) : "l"(a), "l"(b), "l"(c));
    return d;
}
__device__ __forceinline__ void upk2(u64 v, float &lo, float &hi) {
    asm("mov.b64 {%0, %1}, %2;" : "=f"(lo), "=f"(hi) : "l"(v));
}
__device__ __forceinline__ void cpa16(float *s, const float *g) {
    unsigned ss = (unsigned)__cvta_generic_to_shared(s);
    asm volatile("cp.async.ca.shared.global [%0], [%1], 16;" :: "r"(ss), "l"(g));
}
__device__ __forceinline__ void cp_commit() {
    asm volatile("cp.async.commit_group;");
}
__device__ __forceinline__ void cp_wait0() {
    asm volatile("cp.async.wait_group 0;");
}
__device__ __forceinline__ void cp_wait1() {
    asm volatile("cp.async.wait_group 1;");
}

// Compute `rows` k-steps from staged weight buffer `buf` ([rows][256]),
// activations from sA (first kA k-rows) then sB (skip-concat tail), both K-major
// with row stride 64 floats.
__device__ __forceinline__ void compute_rows(
    int rows, int k0, int kA,
    const float *__restrict__ sA, const float *__restrict__ sB,
    const float *__restrict__ buf,
    u64 acc[4][8], int tr, int tc)
{
#pragma unroll 4
    for (int kk = 0; kk < rows; kk++) {
        int kg = k0 + kk;
        const float *hr = (kg < kA) ? (sA + kg * 64) : (sB + (kg - kA) * 64);
        float4 av = *(const float4 *)(hr + 4 * tr);
        u64 a0 = pk2(av.x, av.x);
        u64 a1 = pk2(av.y, av.y);
        u64 a2 = pk2(av.z, av.z);
        u64 a3 = pk2(av.w, av.w);
        const float *wr = buf + kk * 256 + 4 * tc;
#pragma unroll
        for (int q = 0; q < 4; q++) {
            float4 wv = *(const float4 *)(wr + 64 * q);
            u64 w0 = pk2(wv.x, wv.y);
            u64 w1 = pk2(wv.z, wv.w);
            acc[0][2 * q]     = fma2(a0, w0, acc[0][2 * q]);
            acc[0][2 * q + 1] = fma2(a0, w1, acc[0][2 * q + 1]);
            acc[1][2 * q]     = fma2(a1, w0, acc[1][2 * q]);
            acc[1][2 * q + 1] = fma2(a1, w1, acc[1][2 * q + 1]);
            acc[2][2 * q]     = fma2(a2, w0, acc[2][2 * q]);
            acc[2][2 * q + 1] = fma2(a2, w1, acc[2][2 * q + 1]);
            acc[3][2 * q]     = fma2(a3, w0, acc[3][2 * q]);
            acc[3][2 * q + 1] = fma2(a3, w1, acc[3][2 * q + 1]);
        }
    }
}

// One hidden layer: hout[c][m] = relu(b[c] + sum_k src[k][m] * w[k][c]),
// K = kA + kB rows of w (kA from sA, kB from sB).
__device__ __forceinline__ void run_layer(
    const float *__restrict__ gw, const float *__restrict__ gb,
    const float *__restrict__ sA, int kA,
    const float *__restrict__ sB, int kB,
    float *__restrict__ hout,
    float *__restrict__ wb, float *__restrict__ bs,
    int tid, int tr, int tc)
{
    const int K = kA + kB;
    const int nck = (K + KC - 1) / KC;

    // stage chunk 0
    {
        int rows = (K < KC) ? K : KC;
        for (int i = tid; i < rows * 64; i += THREADS)
            cpa16(wb + i * 4, gw + i * 4);
        cp_commit();
    }
    // stage bias (256 floats) with plain loads
    if (tid < 64)
        ((float4 *)bs)[tid] = ((const float4 *)gb)[tid];

    u64 acc[4][8];
    bool first = true;

    for (int ck = 0; ck < nck; ck++) {
        const float *buf = wb + (ck & 1) * (KC * 256);
        if (ck + 1 < nck) {
            float *nbuf = wb + ((ck + 1) & 1) * (KC * 256);
            const float *gsrc = gw + (ck + 1) * KC * 256;
            int nrows = K - (ck + 1) * KC;
            if (nrows > KC) nrows = KC;
            for (int i = tid; i < nrows * 64; i += THREADS)
                cpa16(nbuf + i * 4, gsrc + i * 4);
            cp_commit();
            cp_wait1();
        } else {
            cp_wait0();
        }
        __syncthreads();

        if (first) {
            first = false;
#pragma unroll
            for (int p = 0; p < 8; p++) {
                int c0 = 4 * tc + 64 * (p >> 1) + 2 * (p & 1);
                u64 bb = pk2(bs[c0], bs[c0 + 1]);
                acc[0][p] = bb; acc[1][p] = bb; acc[2][p] = bb; acc[3][p] = bb;
            }
        }

        int k0 = ck * KC;
        int rows = K - k0;
        if (rows > KC) rows = KC;
        if (rows == KC)
            compute_rows(KC, k0, kA, sA, sB, buf, acc, tr, tc);
        else
            compute_rows(rows, k0, kA, sA, sB, buf, acc, tr, tc);
        __syncthreads();   // protect weight buffer reuse
    }

    // epilogue: relu, store col-major into hout
#pragma unroll
    for (int p = 0; p < 8; p++) {
        int c0 = 4 * tc + 64 * (p >> 1) + 2 * (p & 1);
        float v0[4], v1[4];
#pragma unroll
        for (int r = 0; r < 4; r++) {
            float lo, hi;
            upk2(acc[r][p], lo, hi);
            v0[r] = fmaxf(lo, 0.0f);
            v1[r] = fmaxf(hi, 0.0f);
        }
        *(float4 *)(hout + c0 * 64 + 4 * tr) = make_float4(v0[0], v0[1], v0[2], v0[3]);
        *(float4 *)(hout + (c0 + 1) * 64 + 4 * tr) = make_float4(v1[0], v1[1], v1[2], v1[3]);
    }
    __syncthreads();
}

__global__ void __launch_bounds__(THREADS, 1) mlp_fused_kernel(
    const float *__restrict__ x,
    const float *__restrict__ w1, const float *__restrict__ b1,
    const float *__restrict__ w2, const float *__restrict__ b2,
    const float *__restrict__ w3, const float *__restrict__ b3,
    const float *__restrict__ w4, const float *__restrict__ b4,
    const float *__restrict__ w5, const float *__restrict__ b5,
    const float *__restrict__ w6, const float *__restrict__ b6,
    const float *__restrict__ w7, const float *__restrict__ b7,
    const float *__restrict__ w8, const float *__restrict__ b8,
    const float *__restrict__ w9, const float *__restrict__ b9,
    float *__restrict__ out)
{
    extern __shared__ float smem[];
    float *hA = smem;                  // 256*64
    float *hB = hA + 256 * 64;         // 256*64
    float *xs = hB + 256 * 64;         // 40*64 (row 39 zero pad)
    float *wb = xs + 40 * 64;          // 2*KC*256
    float *bs = wb + 2 * KC * 256;     // 256

    const int tid = threadIdx.x;
    const int tr = tid >> 4;           // 0..15: row group (4 rows each)
    const int tc = tid & 15;           // 0..15: col group (16 cols each, strided)
    const int row0 = blockIdx.x * M_TILE;

    // stage x tile K-major: xs[k][m]
    for (int i = tid; i < M_TILE * 40; i += THREADS) {
        int m = i / 40, k = i % 40;
        xs[k * 64 + m] = (k < IN_DIM) ? x[(size_t)(row0 + m) * IN_DIM + k] : 0.0f;
    }
    __syncthreads();

    const float *Wl[8] = {w1, w2, w3, w4, w5, w6, w7, w8};
    const float *Bl[8] = {b1, b2, b3, b4, b5, b6, b7, b8};
    float *io[2] = {hA, hB};

    const float *in = xs;
    int kA = IN_DIM;
    for (int l = 0; l < 8; l++) {
        float *o = io[l & 1];                       // l=0 -> hA, l=1 -> hB, ...
        int kB = (l == 4) ? IN_DIM : 0;             // layer 5: skip concat with x
        run_layer(Wl[l], Bl[l], in, kA, xs, kB, o, wb, bs, tid, tr, tc);
        in = o;
        kA = HID;
    }
    // `in` == hB here (layer-8 output)

    // Layer 9: [256 -> 4], one output per thread.
    if (tid < 256)
        ((float4 *)wb)[tid] = ((const float4 *)w9)[tid];   // 256x4 floats
    __syncthreads();

    {
        int m = tid >> 2;
        int c = tid & 3;
        float s0 = 0.f, s1 = 0.f, s2 = 0.f, s3 = 0.f;
        const float *hin = in;
#pragma unroll 4
        for (int k = 0; k < HID; k += 4) {
            s0 += hin[(k + 0) * 64 + m] * wb[(k + 0) * 4 + c];
            s1 += hin[(k + 1) * 64 + m] * wb[(k + 1) * 4 + c];
            s2 += hin[(k + 2) * 64 + m] * wb[(k + 2) * 4 + c];
            s3 += hin[(k + 3) * 64 + m] * wb[(k + 3) * 4 + c];
        }
        out[(size_t)(row0 + m) * OUT_DIM + c] = (s0 + s1) + (s2 + s3) + b9[c];
    }
}

extern "C" void kernel_launch(void *const *d_in, const int *in_sizes, int n_in,
                              void *d_out, int out_size)
{
    const float *x  = (const float *)d_in[0];
    const float *w1 = (const float *)d_in[1],  *b1 = (const float *)d_in[2];
    const float *w2 = (const float *)d_in[3],  *b2 = (const float *)d_in[4];
    const float *w3 = (const float *)d_in[5],  *b3 = (const float *)d_in[6];
    const float *w4 = (const float *)d_in[7],  *b4 = (const float *)d_in[8];
    const float *w5 = (const float *)d_in[9],  *b5 = (const float *)d_in[10];
    const float *w6 = (const float *)d_in[11], *b6 = (const float *)d_in[12];
    const float *w7 = (const float *)d_in[13], *b7 = (const float *)d_in[14];
    const float *w8 = (const float *)d_in[15], *b8 = (const float *)d_in[16];
    const float *w9 = (const float *)d_in[17], *b9 = (const float *)d_in[18];
    float *out = (float *)d_out;

    // smem: 2*16384 + 2560 + 16384 + 256 floats = 207,872 bytes
    const int smem_bytes = (2 * 256 * 64 + 40 * 64 + 2 * KC * 256 + 256) * (int)sizeof(float);
    cudaFuncSetAttribute(mlp_fused_kernel,
                         cudaFuncAttributeMaxDynamicSharedMemorySize, smem_bytes);

    dim3 grid(NROWS / M_TILE);   // 4096
    dim3 block(THREADS);
    mlp_fused_kernel<<<grid, block, smem_bytes>>>(
        x, w1, b1, w2, b2, w3, b3, w4, b4, w5, b5,
        w6, b6, w7, b7, w8, b8, w9, b9, out);
}

// round 4
// speedup vs baseline: 2.7056x; 2.7056x over previous
#include <cuda_runtime.h>
#include <cuda_bf16.h>
#include <cstdint>

// Fused 9-layer MLP via mma.sync bf16 (HMMA), split-bf16 hi/lo for fp32 accuracy.
// N=262144, IN=39(pad64), H=256, OUT=4. CTA = 64 rows, 256 threads (8 warps).
// Warp tile 32x64; C in registers; activations in-place in padded smem;
// weights pre-split+transposed to [k][n] chunks, cp.async double-buffered.
// R4 fix: A operand offset by chunk index (64*c cols); 256B-align weight chunks.

#define THREADS 256
#define M_TILE  64
#define NROWS   262144

// 30 chunks of [64 k][256 n] bf16 each (row-major, k-major rows)
__device__ __align__(256) __nv_bfloat16 g_whi[30 * 16384];
__device__ __align__(256) __nv_bfloat16 g_wlo[30 * 16384];

// ---- smem byte layout ----
#define WBUF_SZ  67584              // per buf: hi 64*528 + lo 64*528
#define SM_W     0                  // 2 bufs = 135168
#define SM_A     135168             // hi 33792
#define SM_A_LO  168960             // lo 33792  (A = [64 rows][264 cols] bf16)
#define SM_X     202752             // hi 9216   (x = [64 rows][72 cols] bf16)
#define SM_X_LO  211968             // lo 9216
#define SM_BIAS  221184             // 256 fp32
#define SM_W9    222208             // 1024 fp32
#define SM_TOTAL 226368

#define ASTR 528     // A row stride bytes (264 bf16)
#define XSTR 144     // x row stride bytes (72 bf16)
#define WSTR 528     // W smem row stride bytes (264 bf16, data in first 512B)

// ---------- PTX helpers (all baseline, no 'a' features) ----------
__device__ __forceinline__ uint32_t smem_u32(const void* p) {
    uint32_t a;
    asm("{ .reg .u64 t; cvta.to.shared.u64 t, %1; cvt.u32.u64 %0, t; }" : "=r"(a) : "l"(p));
    return a;
}
__device__ __forceinline__ void cpa16(uint8_t* s, const uint8_t* g) {
    uint32_t ss = smem_u32(s);
    asm volatile("cp.async.cg.shared.global [%0], [%1], 16;" :: "r"(ss), "l"(g));
}
__device__ __forceinline__ void cp_commit() { asm volatile("cp.async.commit_group;"); }
__device__ __forceinline__ void cp_wait0()  { asm volatile("cp.async.wait_group 0;"); }
__device__ __forceinline__ void cp_wait1()  { asm volatile("cp.async.wait_group 1;"); }

__device__ __forceinline__ void ldsm4(uint32_t* r, uint32_t addr) {
    asm volatile("ldmatrix.sync.aligned.m8n8.x4.shared.b16 {%0,%1,%2,%3}, [%4];"
                 : "=r"(r[0]), "=r"(r[1]), "=r"(r[2]), "=r"(r[3]) : "r"(addr));
}
__device__ __forceinline__ void ldsm4t(uint32_t* r, uint32_t addr) {
    asm volatile("ldmatrix.sync.aligned.m8n8.x4.trans.shared.b16 {%0,%1,%2,%3}, [%4];"
                 : "=r"(r[0]), "=r"(r[1]), "=r"(r[2]), "=r"(r[3]) : "r"(addr));
}
__device__ __forceinline__ void mma_bf16(float* c, const uint32_t* a, uint32_t b0, uint32_t b1) {
    asm volatile(
        "mma.sync.aligned.m16n8k16.row.col.f32.bf16.bf16.f32 "
        "{%0,%1,%2,%3}, {%4,%5,%6,%7}, {%8,%9}, {%0,%1,%2,%3};"
        : "+f"(c[0]), "+f"(c[1]), "+f"(c[2]), "+f"(c[3])
        : "r"(a[0]), "r"(a[1]), "r"(a[2]), "r"(a[3]), "r"(b0), "r"(b1));
}

__device__ __forceinline__ uint32_t split_pack_hi(float v0, float v1,
                                                  uint32_t& lo_out) {
    __nv_bfloat16 h0 = __float2bfloat16_rn(v0);
    __nv_bfloat16 h1 = __float2bfloat16_rn(v1);
    __nv_bfloat16 l0 = __float2bfloat16_rn(v0 - __bfloat162float(h0));
    __nv_bfloat16 l1 = __float2bfloat16_rn(v1 - __bfloat162float(h1));
    lo_out = ((uint32_t)__bfloat16_as_ushort(l1) << 16) | __bfloat16_as_ushort(l0);
    return ((uint32_t)__bfloat16_as_ushort(h1) << 16) | __bfloat16_as_ushort(h0);
}

// ---------- prep: fp32 weights -> split bf16 [k][n] chunks ----------
__global__ void __launch_bounds__(256) prep_kernel(
    const float* __restrict__ w1, const float* __restrict__ w2,
    const float* __restrict__ w3, const float* __restrict__ w4,
    const float* __restrict__ w5, const float* __restrict__ w6,
    const float* __restrict__ w7, const float* __restrict__ w8)
{
    int gid = blockIdx.x * 256 + threadIdx.x;   // 0 .. 491519
    int chunk = gid >> 14;
    int e = gid & 16383;
    int kl = e >> 8;       // k within chunk (0..63)
    int r  = e & 255;      // n (0..255)
    const float* src; int k0, Ksrc;
    if (chunk == 0)      { src = w1; k0 = 0;                 Ksrc = 39;  }
    else if (chunk < 5)  { src = w2; k0 = (chunk - 1) * 64;  Ksrc = 256; }
    else if (chunk < 9)  { src = w3; k0 = (chunk - 5) * 64;  Ksrc = 256; }
    else if (chunk < 13) { src = w4; k0 = (chunk - 9) * 64;  Ksrc = 256; }
    else if (chunk < 18) { src = w5; k0 = (chunk - 13) * 64; Ksrc = 295; }
    else if (chunk < 22) { src = w6; k0 = (chunk - 18) * 64; Ksrc = 256; }
    else if (chunk < 26) { src = w7; k0 = (chunk - 22) * 64; Ksrc = 256; }
    else                 { src = w8; k0 = (chunk - 26) * 64; Ksrc = 256; }
    int k = k0 + kl;
    float v = (k < Ksrc) ? src[k * 256 + r] : 0.0f;
    __nv_bfloat16 hi = __float2bfloat16_rn(v);
    __nv_bfloat16 lo = __float2bfloat16_rn(v - __bfloat162float(hi));
    g_whi[gid] = hi;
    g_wlo[gid] = lo;
}

// ---------- main fused kernel ----------
__device__ __forceinline__ void stage_chunk(uint8_t* sm, int buf, int chunk, int tid) {
    const uint8_t* shi = (const uint8_t*)(g_whi + chunk * 16384);
    const uint8_t* slo = (const uint8_t*)(g_wlo + chunk * 16384);
    uint8_t* d = sm + SM_W + buf * WBUF_SZ;
#pragma unroll
    for (int i = tid; i < 2048; i += THREADS) {
        int row = i >> 5, j = i & 31;
        int doff = row * WSTR + j * 16;
        cpa16(d + doff,          shi + i * 16);
        cpa16(d + 33792 + doff,  slo + i * 16);
    }
    cp_commit();
}

__device__ __forceinline__ void compute_chunk(
    float C[2][8][4],
    uint32_t ah_base, uint32_t al_base, int astr,
    uint32_t wh_base, uint32_t wl_base,
    int lane, int row0w, int col0w)
{
    const int quad = lane >> 3;
    const int qr   = lane & 7;
    const int arow_off = ((quad & 1) << 3) + qr;   // row within 16-tile
    const int acol_off = (quad >> 1) << 3;         // k offset within 16
    const int brow_off = ((quad & 1) << 3) + qr;   // k within 16-tile
    const int bcol_off = (quad >> 1) << 3;         // n offset within 16

#pragma unroll
    for (int ks = 0; ks < 4; ks++) {
        const int k0 = ks * 16;
        uint32_t ah[2][4], al[2][4];
#pragma unroll
        for (int mf = 0; mf < 2; mf++) {
            int row = row0w + mf * 16 + arow_off;
            int kk  = k0 + acol_off;
            uint32_t off = (uint32_t)(row * astr + kk * 2);
            ldsm4(ah[mf], ah_base + off);
            ldsm4(al[mf], al_base + off);
        }
#pragma unroll
        for (int np = 0; np < 4; np++) {
            int krow = k0 + brow_off;
            int ncol = col0w + np * 16 + bcol_off;
            uint32_t woff = (uint32_t)(krow * WSTR + ncol * 2);
            uint32_t bh[4], bl[4];
            ldsm4t(bh, wh_base + woff);
            ldsm4t(bl, wl_base + woff);
#pragma unroll
            for (int mf = 0; mf < 2; mf++) {
#pragma unroll
                for (int ns = 0; ns < 2; ns++) {
                    float* cc = C[mf][np * 2 + ns];
                    mma_bf16(cc, ah[mf], bh[2 * ns], bh[2 * ns + 1]);
                    mma_bf16(cc, ah[mf], bl[2 * ns], bl[2 * ns + 1]);
                    mma_bf16(cc, al[mf], bh[2 * ns], bh[2 * ns + 1]);
                }
            }
        }
    }
}

__global__ void __launch_bounds__(THREADS, 1) mlp_mma_kernel(
    const float* __restrict__ x,
    const float* __restrict__ b1, const float* __restrict__ b2,
    const float* __restrict__ b3, const float* __restrict__ b4,
    const float* __restrict__ b5, const float* __restrict__ b6,
    const float* __restrict__ b7, const float* __restrict__ b8,
    const float* __restrict__ w9, const float* __restrict__ b9,
    float* __restrict__ out)
{
    extern __shared__ uint8_t sm[];
    const int tid  = threadIdx.x;
    const int wid  = tid >> 5;
    const int lane = tid & 31;
    const int row0w = (wid & 1) * 32;   // warp m-offset
    const int col0w = (wid >> 1) * 64;  // warp n-offset
    const int row0 = blockIdx.x * M_TILE;

    float* bsm = (float*)(sm + SM_BIAS);
    float* w9s = (float*)(sm + SM_W9);
    const uint32_t a_hi = smem_u32(sm + SM_A);
    const uint32_t a_lo = smem_u32(sm + SM_A_LO);
    const uint32_t x_hi = smem_u32(sm + SM_X);
    const uint32_t x_lo = smem_u32(sm + SM_X_LO);

    static const int CB[8]  = {0, 1, 5, 9, 13, 18, 22, 26};
    static const int NCK[8] = {1, 4, 4, 4, 5,  4,  4,  4};

    // prologue: stage chunk 0 into buf 0
    stage_chunk(sm, 0, 0, tid);

    // stage x tile (split bf16) and w9
    {
        __nv_bfloat16* xh = (__nv_bfloat16*)(sm + SM_X);
        __nv_bfloat16* xl = (__nv_bfloat16*)(sm + SM_X_LO);
        for (int i = tid; i < M_TILE * 64; i += THREADS) {
            int r = i >> 6, k = i & 63;
            float v = (k < 39) ? x[(size_t)(row0 + r) * 39 + k] : 0.0f;
            __nv_bfloat16 hi = __float2bfloat16_rn(v);
            __nv_bfloat16 lo = __float2bfloat16_rn(v - __bfloat162float(hi));
            xh[r * 72 + k] = hi;
            xl[r * 72 + k] = lo;
        }
        for (int i = tid; i < 1024; i += THREADS) w9s[i] = w9[i];
    }

    const float* Bl[8] = {b1, b2, b3, b4, b5, b6, b7, b8};
    int bi = 0;

    for (int l = 0; l < 8; l++) {
        bsm[tid] = (tid < 256) ? Bl[l][tid] : 0.0f;   // tid always <256

        float C[2][8][4];
#pragma unroll
        for (int i = 0; i < 2; i++)
#pragma unroll
            for (int j = 0; j < 8; j++)
#pragma unroll
                for (int q = 0; q < 4; q++) C[i][j][q] = 0.0f;

        const int nck = NCK[l];
        for (int c = 0; c < nck; c++) {
            int nxt = (c + 1 < nck) ? (CB[l] + c + 1) : ((l < 7) ? CB[l + 1] : -1);
            if (nxt >= 0) { stage_chunk(sm, bi ^ 1, nxt, tid); cp_wait1(); }
            else          { cp_wait0(); }
            __syncthreads();

            const uint32_t wh = smem_u32(sm + SM_W + bi * WBUF_SZ);
            const uint32_t wl = wh + 33792;
            const bool usex = (l == 0) || (l == 4 && c == 4);
            // R4 FIX: chunk c of a multi-chunk layer reads A k-range [64c, 64c+63]
            const uint32_t akoff = usex ? 0u : (uint32_t)(c * 128);  // 64 cols * 2B
            compute_chunk(C,
                          (usex ? x_hi : a_hi) + akoff,
                          (usex ? x_lo : a_lo) + akoff,
                          usex ? XSTR : ASTR,
                          wh, wl, lane, row0w, col0w);
            __syncthreads();
            bi ^= 1;
        }

        if (l < 7) {
            // epilogue: bias + relu + split, write A in place
#pragma unroll
            for (int mf = 0; mf < 2; mf++) {
#pragma unroll
                for (int nf = 0; nf < 8; nf++) {
                    int col = col0w + nf * 8 + 2 * (lane & 3);
                    int rA  = row0w + mf * 16 + (lane >> 2);
                    float* cc = C[mf][nf];
                    float v0 = fmaxf(cc[0] + bsm[col],     0.0f);
                    float v1 = fmaxf(cc[1] + bsm[col + 1], 0.0f);
                    float v2 = fmaxf(cc[2] + bsm[col],     0.0f);
                    float v3 = fmaxf(cc[3] + bsm[col + 1], 0.0f);
                    uint32_t lo01, lo23;
                    uint32_t hi01 = split_pack_hi(v0, v1, lo01);
                    uint32_t hi23 = split_pack_hi(v2, v3, lo23);
                    uint32_t off  = (uint32_t)(rA * ASTR + col * 2);
                    uint32_t off2 = off + 8u * ASTR;
                    *(uint32_t*)(sm + SM_A    + off)  = hi01;
                    *(uint32_t*)(sm + SM_A_LO + off)  = lo01;
                    *(uint32_t*)(sm + SM_A    + off2) = hi23;
                    *(uint32_t*)(sm + SM_A_LO + off2) = lo23;
                }
            }
            __syncthreads();
        } else {
            // final epilogue: relu(h)+bias, then x w9 (256->4), reduce via smem atomics
            float* scr = (float*)sm;            // 256 floats (W bufs dead now)
            scr[tid] = 0.0f;
            __syncthreads();
            float p[4][4];
#pragma unroll
            for (int i = 0; i < 4; i++)
#pragma unroll
                for (int j = 0; j < 4; j++) p[i][j] = 0.0f;
#pragma unroll
            for (int mf = 0; mf < 2; mf++) {
#pragma unroll
                for (int nf = 0; nf < 8; nf++) {
                    int col = col0w + nf * 8 + 2 * (lane & 3);
                    float* cc = C[mf][nf];
                    float v0 = fmaxf(cc[0] + bsm[col],     0.0f);
                    float v1 = fmaxf(cc[1] + bsm[col + 1], 0.0f);
                    float v2 = fmaxf(cc[2] + bsm[col],     0.0f);
                    float v3 = fmaxf(cc[3] + bsm[col + 1], 0.0f);
                    const float* wc0 = w9s + col * 4;
                    const float* wc1 = w9s + (col + 1) * 4;
#pragma unroll
                    for (int j = 0; j < 4; j++) {
                        p[2 * mf][j]     += v0 * wc0[j] + v1 * wc1[j];
                        p[2 * mf + 1][j] += v2 * wc0[j] + v3 * wc1[j];
                    }
                }
            }
#pragma unroll
            for (int rr = 0; rr < 4; rr++) {
                int row = row0w + (rr >> 1) * 16 + (rr & 1) * 8 + (lane >> 2);
#pragma unroll
                for (int j = 0; j < 4; j++)
                    atomicAdd(scr + row * 4 + j, p[rr][j]);
            }
            __syncthreads();
            out[(size_t)(row0 + (tid >> 2)) * 4 + (tid & 3)] = scr[tid] + b9[tid & 3];
        }
    }
}

extern "C" void kernel_launch(void* const* d_in, const int* in_sizes, int n_in,
                              void* d_out, int out_size)
{
    const float* x  = (const float*)d_in[0];
    const float* w1 = (const float*)d_in[1],  *b1 = (const float*)d_in[2];
    const float* w2 = (const float*)d_in[3],  *b2 = (const float*)d_in[4];
    const float* w3 = (const float*)d_in[5],  *b3 = (const float*)d_in[6];
    const float* w4 = (const float*)d_in[7],  *b4 = (const float*)d_in[8];
    const float* w5 = (const float*)d_in[9],  *b5 = (const float*)d_in[10];
    const float* w6 = (const float*)d_in[11], *b6 = (const float*)d_in[12];
    const float* w7 = (const float*)d_in[13], *b7 = (const float*)d_in[14];
    const float* w8 = (const float*)d_in[15], *b8 = (const float*)d_in[16];
    const float* w9 = (const float*)d_in[17], *b9 = (const float*)d_in[18];
    float* out = (float*)d_out;

    prep_kernel<<<1920, 256>>>(w1, w2, w3, w4, w5, w6, w7, w8);

    cudaFuncSetAttribute(mlp_mma_kernel,
                         cudaFuncAttributeMaxDynamicSharedMemorySize, SM_TOTAL);
    mlp_mma_kernel<<<NROWS / M_TILE, THREADS, SM_TOTAL>>>(
        x, b1, b2, b3, b4, b5, b6, b7, b8, w9, b9, out);
}